// round 2
// baseline (speedup 1.0000x reference)
#include <cuda_runtime.h>
#include <cuda_bf16.h>
#include <math.h>

// Problem dims
#define B 64
#define TT 512
#define E 128
#define H 256

// ---------------- scratch (device globals; no allocation allowed) -------------
__device__ float g_xp1f[(size_t)B * TT * H];   // 32MB
__device__ float g_xp1b[(size_t)B * TT * H];
__device__ float g_o1[(size_t)B * TT * 2 * H]; // 64MB
__device__ float g_xp2f[(size_t)B * TT * H];
__device__ float g_xp2b[(size_t)B * TT * H];
__device__ float g_o2[(size_t)B * TT * 2 * H]; // 64MB

__device__ float g_wT1f[E * H];       // [k][j]
__device__ float g_wT1b[E * H];
__device__ float g_wT2f[2 * H * H];   // [k][j], k<512
__device__ float g_wT2b[2 * H * H];
__device__ float g_b1f[H], g_b1b[H], g_b2f[H], g_b2b[H];
__device__ float g_w1T[1024 * 512];   // [k][o]
__device__ float g_w2T[512 * 256];    // [k][o]

// ---------------- prep: transposes + bias combine -----------------------------
__global__ void prep_kernel(
    const float* __restrict__ r1_wif, const float* __restrict__ r1_wib,
    const float* __restrict__ r1_bif, const float* __restrict__ r1_bhf,
    const float* __restrict__ r1_bib, const float* __restrict__ r1_bhb,
    const float* __restrict__ r2_wif, const float* __restrict__ r2_wib,
    const float* __restrict__ r2_bif, const float* __restrict__ r2_bhf,
    const float* __restrict__ r2_bib, const float* __restrict__ r2_bhb,
    const float* __restrict__ w1, const float* __restrict__ w2)
{
    int i = blockIdx.x * 256 + threadIdx.x;
    if (i < E * H) {                       // wT1[k*256+j] = w[j*128+k]
        int k = i >> 8, j = i & 255;
        g_wT1f[i] = r1_wif[j * E + k];
        g_wT1b[i] = r1_wib[j * E + k];
    }
    if (i < 2 * H * H) {                   // wT2[k*256+j] = w[j*512+k]
        int k = i >> 8, j = i & 255;
        g_wT2f[i] = r2_wif[j * (2 * H) + k];
        g_wT2b[i] = r2_wib[j * (2 * H) + k];
        // w2T[k*256+o] = w2[o*512+k] (same index space 512*256)
        g_w2T[i] = w2[(i & 255) * 512 + (i >> 8)];
    }
    if (i < 1024 * 512) {                  // w1T[k*512+o] = w1[o*1024+k]
        int k = i >> 9, o = i & 511;
        g_w1T[i] = w1[o * 1024 + k];
    }
    if (i < H) {
        g_b1f[i] = r1_bif[i] + r1_bhf[i];
        g_b1b[i] = r1_bib[i] + r1_bhb[i];
        g_b2f[i] = r2_bif[i] + r2_bhf[i];
        g_b2b[i] = r2_bib[i] + r2_bhb[i];
    }
}

// ---------------- layer-1 input projection (embedding gather fused) -----------
__global__ __launch_bounds__(256) void proj1_kernel(
    const int* __restrict__ x, const float* __restrict__ emb)
{
    __shared__ float e[8][E];
    int b = blockIdx.y, t0 = blockIdx.x * 8;
    int tid = threadIdx.x;
    for (int i = tid; i < 8 * E; i += 256) {
        int tt = i >> 7, k = i & 127;
        int idx = x[b * TT + t0 + tt];
        e[tt][k] = emb[(size_t)idx * E + k];
    }
    __syncthreads();
    int j = tid;
    float af[8], ab[8];
#pragma unroll
    for (int tt = 0; tt < 8; tt++) { af[tt] = g_b1f[j]; ab[tt] = g_b1b[j]; }
#pragma unroll 4
    for (int k = 0; k < E; k++) {
        float wf = g_wT1f[k * H + j];
        float wb = g_wT1b[k * H + j];
#pragma unroll
        for (int tt = 0; tt < 8; tt++) {
            float ev = e[tt][k];
            af[tt] += ev * wf;
            ab[tt] += ev * wb;
        }
    }
#pragma unroll
    for (int tt = 0; tt < 8; tt++) {
        size_t o = ((size_t)(b * TT + t0 + tt)) * H + j;
        g_xp1f[o] = af[tt];
        g_xp1b[o] = ab[tt];
    }
}

// ---------------- layer-2 input projection ------------------------------------
__global__ __launch_bounds__(256) void proj2_kernel()
{
    __shared__ float e[8 * 2 * H];  // 16KB
    int b = blockIdx.y, t0 = blockIdx.x * 8;
    const float* in = g_o1 + ((size_t)(b * TT + t0)) * (2 * H);
    for (int i = threadIdx.x; i < 8 * 2 * H; i += 256) e[i] = in[i];
    __syncthreads();
    int j = threadIdx.x;
    float af[8], ab[8];
#pragma unroll
    for (int tt = 0; tt < 8; tt++) { af[tt] = g_b2f[j]; ab[tt] = g_b2b[j]; }
#pragma unroll 4
    for (int k = 0; k < 2 * H; k++) {
        float wf = g_wT2f[k * H + j];
        float wb = g_wT2b[k * H + j];
#pragma unroll
        for (int tt = 0; tt < 8; tt++) {
            float ev = e[tt * (2 * H) + k];
            af[tt] += ev * wf;
            ab[tt] += ev * wb;
        }
    }
#pragma unroll
    for (int tt = 0; tt < 8; tt++) {
        size_t o = ((size_t)(b * TT + t0 + tt)) * H + j;
        g_xp2f[o] = af[tt];
        g_xp2b[o] = ab[tt];
    }
}

// ---------------- recurrence: one CTA per (batch, direction) ------------------
// thread j computes output neuron j. Row whh[j][:]: first WREG k's in registers,
// remaining WSM k's in shared memory laid out [k][j] (conflict-free).
// h is double-buffered in smem, read via broadcast float4.
constexpr int WREG = 160;
constexpr int WSM = H - WREG;  // 96
constexpr int RNN_SMEM_BYTES = (WSM * H + 2 * H) * 4;  // 100,352 B

__global__ __launch_bounds__(256, 1) void rnn_kernel(
    const float* __restrict__ whh_f, const float* __restrict__ whh_b, int layer)
{
    extern __shared__ float sm[];
    float* ws = sm;               // [WSM][256]
    float* hb = sm + WSM * H;     // [2][256]

    int b = blockIdx.x >> 1;
    int dir = blockIdx.x & 1;
    const float* whh = dir ? whh_b : whh_f;
    const float* xp = layer ? (dir ? g_xp2b : g_xp2f) : (dir ? g_xp1b : g_xp1f);
    float* out = layer ? g_o2 : g_o1;

    int j = threadIdx.x;
    float wr[WREG];
#pragma unroll
    for (int r = 0; r < WREG; r++) wr[r] = whh[j * H + r];
    for (int r = 0; r < WSM; r++) ws[r * H + j] = whh[j * H + WREG + r];
    hb[j] = 0.f;
    hb[H + j] = 0.f;
    __syncthreads();

    const float* xpBase = xp + (size_t)b * TT * H + j;
    float* outBase = out + (size_t)b * TT * (2 * H) + dir * H + j;

    int p = 0;
    for (int s = 0; s < TT; s++) {
        int t = dir ? (TT - 1 - s) : s;
        float xpv = xpBase[(size_t)t * H];   // issued early, consumed at end
        const float4* h4p = (const float4*)(hb + p * H);
        float a0 = 0.f, a1 = 0.f, a2 = 0.f, a3 = 0.f;
#pragma unroll
        for (int q = 0; q < WREG / 4; q++) {
            float4 h4 = h4p[q];
            a0 += h4.x * wr[4 * q + 0];
            a1 += h4.y * wr[4 * q + 1];
            a2 += h4.z * wr[4 * q + 2];
            a3 += h4.w * wr[4 * q + 3];
        }
#pragma unroll
        for (int q = 0; q < WSM / 4; q++) {
            float4 h4 = h4p[WREG / 4 + q];
            a0 += h4.x * ws[(4 * q + 0) * H + j];
            a1 += h4.y * ws[(4 * q + 1) * H + j];
            a2 += h4.z * ws[(4 * q + 2) * H + j];
            a3 += h4.w * ws[(4 * q + 3) * H + j];
        }
        float hn = tanhf(((a0 + a1) + (a2 + a3)) + xpv);
        hb[(p ^ 1) * H + j] = hn;
        outBase[(size_t)t * (2 * H)] = hn;
        __syncthreads();
        p ^= 1;
    }
}

// ---------------- tail: last/mean + LN + FC1(relu) + FC2 ----------------------
__global__ __launch_bounds__(256) void tail_kernel(
    const float* __restrict__ ln_g, const float* __restrict__ ln_b,
    const float* __restrict__ b1, const float* __restrict__ b2,
    float* __restrict__ outp)
{
    __shared__ float h_s[1024];
    __shared__ float hn_s[1024];
    __shared__ float red[256];
    __shared__ float r_s[512];
    int b = blockIdx.x, j = threadIdx.x;

    const float* base = g_o2 + (size_t)b * TT * (2 * H);
    float s0 = 0.f, s1 = 0.f;
    for (int t = 0; t < TT; t++) {
        s0 += base[(size_t)t * (2 * H) + j];
        s1 += base[(size_t)t * (2 * H) + H + j];
    }
    h_s[j]       = base[(size_t)(TT - 1) * (2 * H) + j];
    h_s[H + j]   = base[(size_t)(TT - 1) * (2 * H) + H + j];
    h_s[512 + j] = s0 * (1.f / 512.f);
    h_s[768 + j] = s1 * (1.f / 512.f);
    __syncthreads();

    // LN mean
    red[j] = h_s[j] + h_s[j + 256] + h_s[j + 512] + h_s[j + 768];
    __syncthreads();
    for (int off = 128; off > 0; off >>= 1) {
        if (j < off) red[j] += red[j + off];
        __syncthreads();
    }
    float mu = red[0] * (1.f / 1024.f);
    __syncthreads();
    // LN var
    float d0 = h_s[j] - mu, d1 = h_s[j + 256] - mu,
          d2 = h_s[j + 512] - mu, d3 = h_s[j + 768] - mu;
    red[j] = d0 * d0 + d1 * d1 + d2 * d2 + d3 * d3;
    __syncthreads();
    for (int off = 128; off > 0; off >>= 1) {
        if (j < off) red[j] += red[j + off];
        __syncthreads();
    }
    float var = red[0] * (1.f / 1024.f);
    float sc = rsqrtf(var + 1e-5f);
    hn_s[j]       = d0 * sc * ln_g[j]       + ln_b[j];
    hn_s[j + 256] = d1 * sc * ln_g[j + 256] + ln_b[j + 256];
    hn_s[j + 512] = d2 * sc * ln_g[j + 512] + ln_b[j + 512];
    hn_s[j + 768] = d3 * sc * ln_g[j + 768] + ln_b[j + 768];
    __syncthreads();

    // FC1: 1024 -> 512, relu
    float a0 = b1[j], a1 = b1[j + 256];
#pragma unroll 4
    for (int k = 0; k < 1024; k++) {
        float hv = hn_s[k];
        a0 += hv * g_w1T[k * 512 + j];
        a1 += hv * g_w1T[k * 512 + j + 256];
    }
    r_s[j]       = fmaxf(a0, 0.f);
    r_s[j + 256] = fmaxf(a1, 0.f);
    __syncthreads();

    // FC2: 512 -> 256
    float a = b2[j];
#pragma unroll 4
    for (int k = 0; k < 512; k++) a += r_s[k] * g_w2T[k * 256 + j];
    outp[b * 256 + j] = a;
}

// ---------------- launch ------------------------------------------------------
extern "C" void kernel_launch(void* const* d_in, const int* in_sizes, int n_in,
                              void* d_out, int out_size)
{
    const int*   x      = (const int*)  d_in[0];
    const float* emb    = (const float*)d_in[1];
    const float* r1_wif = (const float*)d_in[2];
    const float* r1_whf = (const float*)d_in[3];
    const float* r1_bif = (const float*)d_in[4];
    const float* r1_bhf = (const float*)d_in[5];
    const float* r1_wib = (const float*)d_in[6];
    const float* r1_whb = (const float*)d_in[7];
    const float* r1_bib = (const float*)d_in[8];
    const float* r1_bhb = (const float*)d_in[9];
    const float* r2_wif = (const float*)d_in[10];
    const float* r2_whf = (const float*)d_in[11];
    const float* r2_bif = (const float*)d_in[12];
    const float* r2_bhf = (const float*)d_in[13];
    const float* r2_wib = (const float*)d_in[14];
    const float* r2_whb = (const float*)d_in[15];
    const float* r2_bib = (const float*)d_in[16];
    const float* r2_bhb = (const float*)d_in[17];
    const float* ln_g   = (const float*)d_in[18];
    const float* ln_b   = (const float*)d_in[19];
    const float* w1     = (const float*)d_in[20];
    const float* b1     = (const float*)d_in[21];
    const float* w2     = (const float*)d_in[22];
    const float* b2     = (const float*)d_in[23];
    float* outp = (float*)d_out;

    cudaFuncSetAttribute(rnn_kernel,
                         cudaFuncAttributeMaxDynamicSharedMemorySize,
                         RNN_SMEM_BYTES);

    prep_kernel<<<2048, 256>>>(r1_wif, r1_wib, r1_bif, r1_bhf, r1_bib, r1_bhb,
                               r2_wif, r2_wib, r2_bif, r2_bhf, r2_bib, r2_bhb,
                               w1, w2);

    dim3 gproj(TT / 8, B);
    proj1_kernel<<<gproj, 256>>>(x, emb);
    rnn_kernel<<<2 * B, 256, RNN_SMEM_BYTES>>>(r1_whf, r1_whb, 0);
    proj2_kernel<<<gproj, 256>>>();
    rnn_kernel<<<2 * B, 256, RNN_SMEM_BYTES>>>(r2_whf, r2_whb, 1);
    tail_kernel<<<B, 256>>>(ln_g, ln_b, b1, b2, outp);
}

// round 5
// speedup vs baseline: 1.1019x; 1.1019x over previous
#include <cuda_runtime.h>
#include <cuda_bf16.h>
#include <math.h>

#define B 64
#define TT 512
#define E 128
#define H 256

typedef unsigned long long u64;

// ---------------- packed f32x2 helpers ----------------------------------------
__device__ __forceinline__ u64 ffma2(u64 a, u64 b, u64 c) {
    u64 d;
    asm("fma.rn.f32x2 %0, %1, %2, %3;" : "=l"(d) : "l"(a), "l"(b), "l"(c));
    return d;
}
__device__ __forceinline__ u64 fadd2(u64 a, u64 b) {
    u64 d;
    asm("add.rn.f32x2 %0, %1, %2;" : "=l"(d) : "l"(a), "l"(b));
    return d;
}
__device__ __forceinline__ float2 unpk(u64 v) {
    float2 r;
    asm("mov.b64 {%0, %1}, %2;" : "=f"(r.x), "=f"(r.y) : "l"(v));
    return r;
}

// ---------------- scratch (device globals) ------------------------------------
__device__ float g_xp1f[(size_t)B * TT * H];
__device__ float g_xp1b[(size_t)B * TT * H];
__device__ float g_o1[(size_t)B * TT * 2 * H];
__device__ float g_xp2f[(size_t)B * TT * H];
__device__ float g_xp2b[(size_t)B * TT * H];
__device__ float g_o2[(size_t)B * TT * 2 * H];

// pair-packed weights: [k-pair][j] -> float2 {w[2kp][j], w[2kp+1][j]}
__device__ float2 g_p1f[64 * H];
__device__ float2 g_p1b[64 * H];
__device__ float2 g_p2f[256 * H];
__device__ float2 g_p2b[256 * H];
__device__ float2 g_w1p[512 * 512];   // [kp][o], k<1024, o<512
__device__ float2 g_w2p[256 * 256];   // [kp][o], k<512,  o<256
__device__ float g_b1f[H], g_b1b[H], g_b2f[H], g_b2b[H];

// ---------------- prep: pair-packing transposes + bias combine ----------------
__global__ void prep_kernel(
    const float* __restrict__ r1_wif, const float* __restrict__ r1_wib,
    const float* __restrict__ r1_bif, const float* __restrict__ r1_bhf,
    const float* __restrict__ r1_bib, const float* __restrict__ r1_bhb,
    const float* __restrict__ r2_wif, const float* __restrict__ r2_wib,
    const float* __restrict__ r2_bif, const float* __restrict__ r2_bhf,
    const float* __restrict__ r2_bib, const float* __restrict__ r2_bhb,
    const float* __restrict__ w1, const float* __restrict__ w2)
{
    int i = blockIdx.x * 256 + threadIdx.x;
    if (i < 64 * H) {                       // layer-1 in-proj pairs
        int kp = i >> 8, j = i & 255;
        g_p1f[i] = make_float2(r1_wif[j * E + 2 * kp], r1_wif[j * E + 2 * kp + 1]);
        g_p1b[i] = make_float2(r1_wib[j * E + 2 * kp], r1_wib[j * E + 2 * kp + 1]);
    }
    if (i < 256 * H) {                      // layer-2 in-proj pairs + w2 pairs
        int kp = i >> 8, j = i & 255;
        g_p2f[i] = make_float2(r2_wif[j * 512 + 2 * kp], r2_wif[j * 512 + 2 * kp + 1]);
        g_p2b[i] = make_float2(r2_wib[j * 512 + 2 * kp], r2_wib[j * 512 + 2 * kp + 1]);
        g_w2p[i] = make_float2(w2[j * 512 + 2 * kp], w2[j * 512 + 2 * kp + 1]);
    }
    if (i < 512 * 512) {                    // w1 pairs
        int kp = i >> 9, o = i & 511;
        g_w1p[i] = make_float2(w1[o * 1024 + 2 * kp], w1[o * 1024 + 2 * kp + 1]);
    }
    if (i < H) {
        g_b1f[i] = r1_bif[i] + r1_bhf[i];
        g_b1b[i] = r1_bib[i] + r1_bhb[i];
        g_b2f[i] = r2_bif[i] + r2_bhf[i];
        g_b2b[i] = r2_bib[i] + r2_bhb[i];
    }
}

// ---------------- layer-1 input projection (embedding gather fused) -----------
#define TTT 16
__global__ __launch_bounds__(256, 2) void proj1_kernel(
    const int* __restrict__ x, const float* __restrict__ emb)
{
    __shared__ __align__(16) float e[TTT][E];
    int b = blockIdx.y, t0 = blockIdx.x * TTT;
    int tid = threadIdx.x;
    for (int i = tid; i < TTT * E; i += 256) {
        int tt = i >> 7, k = i & 127;
        int idx = x[b * TT + t0 + tt];
        e[tt][k] = emb[(size_t)idx * E + k];
    }
    __syncthreads();
    int j = tid;
    const u64* wfp = (const u64*)g_p1f;
    const u64* wbp = (const u64*)g_p1b;
    u64 accf[TTT], accb[TTT];
#pragma unroll
    for (int tt = 0; tt < TTT; tt++) { accf[tt] = 0ull; accb[tt] = 0ull; }
#pragma unroll 2
    for (int kp = 0; kp < 64; kp++) {
        u64 wfv = wfp[kp * H + j];
        u64 wbv = wbp[kp * H + j];
#pragma unroll
        for (int tt = 0; tt < TTT; tt++) {
            u64 ev = *(const u64*)&e[tt][2 * kp];
            accf[tt] = ffma2(ev, wfv, accf[tt]);
            accb[tt] = ffma2(ev, wbv, accb[tt]);
        }
    }
    float bf = g_b1f[j], bb = g_b1b[j];
#pragma unroll
    for (int tt = 0; tt < TTT; tt++) {
        float2 ff = unpk(accf[tt]);
        float2 fb = unpk(accb[tt]);
        size_t o = ((size_t)(b * TT + t0 + tt)) * H + j;
        g_xp1f[o] = ff.x + ff.y + bf;
        g_xp1b[o] = fb.x + fb.y + bb;
    }
}

// ---------------- layer-2 input projection ------------------------------------
__global__ __launch_bounds__(256, 2) void proj2_kernel()
{
    __shared__ __align__(16) float e[TTT * 2 * H];  // 32KB
    int b = blockIdx.y, t0 = blockIdx.x * TTT;
    const float* in = g_o1 + ((size_t)(b * TT + t0)) * (2 * H);
    for (int i = threadIdx.x; i < TTT * 2 * H; i += 256) e[i] = in[i];
    __syncthreads();
    int j = threadIdx.x;
    const u64* wfp = (const u64*)g_p2f;
    const u64* wbp = (const u64*)g_p2b;
    u64 accf[TTT], accb[TTT];
#pragma unroll
    for (int tt = 0; tt < TTT; tt++) { accf[tt] = 0ull; accb[tt] = 0ull; }
#pragma unroll 2
    for (int kp = 0; kp < 256; kp++) {
        u64 wfv = wfp[kp * H + j];
        u64 wbv = wbp[kp * H + j];
#pragma unroll
        for (int tt = 0; tt < TTT; tt++) {
            u64 ev = *(const u64*)&e[tt * (2 * H) + 2 * kp];
            accf[tt] = ffma2(ev, wfv, accf[tt]);
            accb[tt] = ffma2(ev, wbv, accb[tt]);
        }
    }
    float bf = g_b2f[j], bb = g_b2b[j];
#pragma unroll
    for (int tt = 0; tt < TTT; tt++) {
        float2 ff = unpk(accf[tt]);
        float2 fb = unpk(accb[tt]);
        size_t o = ((size_t)(b * TT + t0 + tt)) * H + j;
        g_xp2f[o] = ff.x + ff.y + bf;
        g_xp2b[o] = fb.x + fb.y + bb;
    }
}

// ---------------- recurrence: one CTA per (batch, direction) ------------------
// 128 k-pairs per neuron row. First 80 pairs in registers, last 48 pairs in
// smem laid out [pair-slot][j] (8B stride, conflict-free). h double-buffered,
// read broadcast as ulonglong2 (two packed pairs per 16B load).
constexpr int PREG = 80;                   // pairs in registers
constexpr int PSM = 128 - PREG;            // 48 pairs in smem
constexpr int RNN_SMEM_BYTES = PSM * H * 8 + 2 * H * 4;  // 100,352 B

__global__ __launch_bounds__(256, 1) void rnn_kernel(
    const float* __restrict__ whh_f, const float* __restrict__ whh_b, int layer)
{
    extern __shared__ char smraw[];
    u64* ws2 = (u64*)smraw;                       // [PSM][256]
    float* hb = (float*)(smraw + PSM * H * 8);    // [2][256]

    int b = blockIdx.x >> 1;
    int dir = blockIdx.x & 1;
    const float* whh = dir ? whh_b : whh_f;
    const float* xp = layer ? (dir ? g_xp2b : g_xp2f) : (dir ? g_xp1b : g_xp1f);
    float* out = layer ? g_o2 : g_o1;

    int j = threadIdx.x;
    const u64* wrow = (const u64*)(whh + (size_t)j * H);  // row j as 128 pairs
    u64 wr[PREG];
#pragma unroll
    for (int r = 0; r < PREG; r++) wr[r] = wrow[r];
    for (int r = 0; r < PSM; r++) ws2[r * H + j] = wrow[PREG + r];
    hb[j] = 0.f;
    hb[H + j] = 0.f;
    __syncthreads();

    const float* xpBase = xp + (size_t)b * TT * H + j;
    float* outBase = out + (size_t)b * TT * (2 * H) + dir * H + j;

    int p = 0;
    for (int s = 0; s < TT; s++) {
        int t = dir ? (TT - 1 - s) : s;
        float xpv = xpBase[(size_t)t * H];   // issued early, consumed at end
        const ulonglong2* h2 = (const ulonglong2*)(hb + p * H);
        u64 a0 = 0ull, a1 = 0ull, a2 = 0ull, a3 = 0ull;
#pragma unroll
        for (int q = 0; q < PREG / 2; q++) {     // pairs 0..79 (reg weights)
            ulonglong2 hq = h2[q];
            if (q & 1) {
                a2 = ffma2(hq.x, wr[2 * q], a2);
                a3 = ffma2(hq.y, wr[2 * q + 1], a3);
            } else {
                a0 = ffma2(hq.x, wr[2 * q], a0);
                a1 = ffma2(hq.y, wr[2 * q + 1], a1);
            }
        }
#pragma unroll
        for (int i = 0; i < PSM / 2; i++) {      // pairs 80..127 (smem weights)
            ulonglong2 hq = h2[PREG / 2 + i];
            u64 w0 = ws2[(2 * i) * H + j];
            u64 w1v = ws2[(2 * i + 1) * H + j];
            if (i & 1) {
                a2 = ffma2(hq.x, w0, a2);
                a3 = ffma2(hq.y, w1v, a3);
            } else {
                a0 = ffma2(hq.x, w0, a0);
                a1 = ffma2(hq.y, w1v, a1);
            }
        }
        float2 f = unpk(fadd2(fadd2(a0, a1), fadd2(a2, a3)));
        float hn = tanhf(f.x + f.y + xpv);
        hb[(p ^ 1) * H + j] = hn;
        outBase[(size_t)t * (2 * H)] = hn;
        __syncthreads();
        p ^= 1;
    }
}

// ---------------- tail: last/mean + LN + FC1(relu) + FC2 ----------------------
__global__ __launch_bounds__(256) void tail_kernel(
    const float* __restrict__ ln_g, const float* __restrict__ ln_b,
    const float* __restrict__ b1, const float* __restrict__ b2,
    float* __restrict__ outp)
{
    __shared__ __align__(16) float h_s[1024];
    __shared__ __align__(16) float hn_s[1024];
    __shared__ float red[256];
    __shared__ __align__(16) float r_s[512];
    int b = blockIdx.x, j = threadIdx.x;

    const float* base = g_o2 + (size_t)b * TT * (2 * H);
    float s0 = 0.f, s1 = 0.f;
    for (int t = 0; t < TT; t++) {
        s0 += base[(size_t)t * (2 * H) + j];
        s1 += base[(size_t)t * (2 * H) + H + j];
    }
    h_s[j]       = base[(size_t)(TT - 1) * (2 * H) + j];
    h_s[H + j]   = base[(size_t)(TT - 1) * (2 * H) + H + j];
    h_s[512 + j] = s0 * (1.f / 512.f);
    h_s[768 + j] = s1 * (1.f / 512.f);
    __syncthreads();

    red[j] = h_s[j] + h_s[j + 256] + h_s[j + 512] + h_s[j + 768];
    __syncthreads();
    for (int off = 128; off > 0; off >>= 1) {
        if (j < off) red[j] += red[j + off];
        __syncthreads();
    }
    float mu = red[0] * (1.f / 1024.f);
    __syncthreads();
    float d0 = h_s[j] - mu, d1 = h_s[j + 256] - mu,
          d2 = h_s[j + 512] - mu, d3 = h_s[j + 768] - mu;
    red[j] = d0 * d0 + d1 * d1 + d2 * d2 + d3 * d3;
    __syncthreads();
    for (int off = 128; off > 0; off >>= 1) {
        if (j < off) red[j] += red[j + off];
        __syncthreads();
    }
    float var = red[0] * (1.f / 1024.f);
    float sc = rsqrtf(var + 1e-5f);
    hn_s[j]       = d0 * sc * ln_g[j]       + ln_b[j];
    hn_s[j + 256] = d1 * sc * ln_g[j + 256] + ln_b[j + 256];
    hn_s[j + 512] = d2 * sc * ln_g[j + 512] + ln_b[j + 512];
    hn_s[j + 768] = d3 * sc * ln_g[j + 768] + ln_b[j + 768];
    __syncthreads();

    // FC1: 1024 -> 512, relu  (pair-packed over k)
    {
        const u64* hnu = (const u64*)hn_s;
        const u64* w1u = (const u64*)g_w1p;
        u64 acc0 = 0ull, acc1 = 0ull;
#pragma unroll 4
        for (int kp = 0; kp < 512; kp++) {
            u64 hv = hnu[kp];
            acc0 = ffma2(hv, w1u[kp * 512 + j], acc0);
            acc1 = ffma2(hv, w1u[kp * 512 + j + 256], acc1);
        }
        float2 f0 = unpk(acc0), f1 = unpk(acc1);
        r_s[j]       = fmaxf(f0.x + f0.y + b1[j], 0.f);
        r_s[j + 256] = fmaxf(f1.x + f1.y + b1[j + 256], 0.f);
    }
    __syncthreads();

    // FC2: 512 -> 256
    {
        const u64* rsu = (const u64*)r_s;
        const u64* w2u = (const u64*)g_w2p;
        u64 acc = 0ull;
#pragma unroll 4
        for (int kp = 0; kp < 256; kp++)
            acc = ffma2(rsu[kp], w2u[kp * 256 + j], acc);
        float2 f = unpk(acc);
        outp[b * 256 + j] = f.x + f.y + b2[j];
    }
}

// ---------------- launch ------------------------------------------------------
extern "C" void kernel_launch(void* const* d_in, const int* in_sizes, int n_in,
                              void* d_out, int out_size)
{
    const int*   x      = (const int*)  d_in[0];
    const float* emb    = (const float*)d_in[1];
    const float* r1_wif = (const float*)d_in[2];
    const float* r1_whf = (const float*)d_in[3];
    const float* r1_bif = (const float*)d_in[4];
    const float* r1_bhf = (const float*)d_in[5];
    const float* r1_wib = (const float*)d_in[6];
    const float* r1_whb = (const float*)d_in[7];
    const float* r1_bib = (const float*)d_in[8];
    const float* r1_bhb = (const float*)d_in[9];
    const float* r2_wif = (const float*)d_in[10];
    const float* r2_whf = (const float*)d_in[11];
    const float* r2_bif = (const float*)d_in[12];
    const float* r2_bhf = (const float*)d_in[13];
    const float* r2_wib = (const float*)d_in[14];
    const float* r2_whb = (const float*)d_in[15];
    const float* r2_bib = (const float*)d_in[16];
    const float* r2_bhb = (const float*)d_in[17];
    const float* ln_g   = (const float*)d_in[18];
    const float* ln_b   = (const float*)d_in[19];
    const float* w1     = (const float*)d_in[20];
    const float* b1     = (const float*)d_in[21];
    const float* w2     = (const float*)d_in[22];
    const float* b2     = (const float*)d_in[23];
    float* outp = (float*)d_out;

    cudaFuncSetAttribute(rnn_kernel,
                         cudaFuncAttributeMaxDynamicSharedMemorySize,
                         RNN_SMEM_BYTES);

    prep_kernel<<<1024, 256>>>(r1_wif, r1_wib, r1_bif, r1_bhf, r1_bib, r1_bhb,
                               r2_wif, r2_wib, r2_bif, r2_bhf, r2_bib, r2_bhb,
                               w1, w2);

    dim3 gproj(TT / TTT, B);
    proj1_kernel<<<gproj, 256>>>(x, emb);
    rnn_kernel<<<2 * B, 256, RNN_SMEM_BYTES>>>(r1_whf, r1_whb, 0);
    proj2_kernel<<<gproj, 256>>>();
    rnn_kernel<<<2 * B, 256, RNN_SMEM_BYTES>>>(r2_whf, r2_whb, 1);
    tail_kernel<<<B, 256>>>(ln_g, ln_b, b1, b2, outp);
}

// round 7
// speedup vs baseline: 1.2768x; 1.1587x over previous
#include <cuda_runtime.h>
#include <cuda_bf16.h>
#include <math.h>

#define B 64
#define TT 512
#define E 128
#define H 256

typedef unsigned long long u64;

// ---------------- packed f32x2 helpers ----------------------------------------
__device__ __forceinline__ u64 ffma2(u64 a, u64 b, u64 c) {
    u64 d;
    asm("fma.rn.f32x2 %0, %1, %2, %3;" : "=l"(d) : "l"(a), "l"(b), "l"(c));
    return d;
}
__device__ __forceinline__ u64 fadd2(u64 a, u64 b) {
    u64 d;
    asm("add.rn.f32x2 %0, %1, %2;" : "=l"(d) : "l"(a), "l"(b));
    return d;
}
__device__ __forceinline__ float2 unpk(u64 v) {
    float2 r;
    asm("mov.b64 {%0, %1}, %2;" : "=f"(r.x), "=f"(r.y) : "l"(v));
    return r;
}

// ---------------- scratch (device globals) ------------------------------------
__device__ float g_xp1f[(size_t)B * TT * H];
__device__ float g_xp1b[(size_t)B * TT * H];
__device__ float g_o1[(size_t)B * TT * 2 * H];
__device__ float g_xp2f[(size_t)B * TT * H];
__device__ float g_xp2b[(size_t)B * TT * H];
__device__ float g_o2[(size_t)B * TT * 2 * H];

// pair-packed weights: [k-pair][j] -> float2 {w[2kp][j], w[2kp+1][j]}
__device__ float2 g_p1f[64 * H];
__device__ float2 g_p1b[64 * H];
__device__ float2 g_p2f[256 * H];
__device__ float2 g_p2b[256 * H];
__device__ float2 g_w1p[512 * 512];   // [kp][o], k<1024, o<512
__device__ float2 g_w2p[256 * 256];   // [kp][o], k<512,  o<256
__device__ float g_b1f[H], g_b1b[H], g_b2f[H], g_b2b[H];

// ---------------- prep: pair-packing transposes + bias combine ----------------
__global__ void prep_kernel(
    const float* __restrict__ r1_wif, const float* __restrict__ r1_wib,
    const float* __restrict__ r1_bif, const float* __restrict__ r1_bhf,
    const float* __restrict__ r1_bib, const float* __restrict__ r1_bhb,
    const float* __restrict__ r2_wif, const float* __restrict__ r2_wib,
    const float* __restrict__ r2_bif, const float* __restrict__ r2_bhf,
    const float* __restrict__ r2_bib, const float* __restrict__ r2_bhb,
    const float* __restrict__ w1, const float* __restrict__ w2)
{
    int i = blockIdx.x * 256 + threadIdx.x;
    if (i < 64 * H) {
        int kp = i >> 8, j = i & 255;
        g_p1f[i] = make_float2(r1_wif[j * E + 2 * kp], r1_wif[j * E + 2 * kp + 1]);
        g_p1b[i] = make_float2(r1_wib[j * E + 2 * kp], r1_wib[j * E + 2 * kp + 1]);
    }
    if (i < 256 * H) {
        int kp = i >> 8, j = i & 255;
        g_p2f[i] = make_float2(r2_wif[j * 512 + 2 * kp], r2_wif[j * 512 + 2 * kp + 1]);
        g_p2b[i] = make_float2(r2_wib[j * 512 + 2 * kp], r2_wib[j * 512 + 2 * kp + 1]);
        g_w2p[i] = make_float2(w2[j * 512 + 2 * kp], w2[j * 512 + 2 * kp + 1]);
    }
    if (i < 512 * 512) {
        int kp = i >> 9, o = i & 511;
        g_w1p[i] = make_float2(w1[o * 1024 + 2 * kp], w1[o * 1024 + 2 * kp + 1]);
    }
    if (i < H) {
        g_b1f[i] = r1_bif[i] + r1_bhf[i];
        g_b1b[i] = r1_bib[i] + r1_bhb[i];
        g_b2f[i] = r2_bif[i] + r2_bhf[i];
        g_b2b[i] = r2_bib[i] + r2_bhb[i];
    }
}

// ---------------- layer-1 input projection: 128 thr, JB=2, TTT=8 --------------
#define TTT 8
__global__ __launch_bounds__(128) void proj1_kernel(
    const int* __restrict__ x, const float* __restrict__ emb)
{
    __shared__ __align__(16) float e[TTT][E];   // 4KB
    int b = blockIdx.y, t0 = blockIdx.x * TTT;
    int tid = threadIdx.x;
    for (int i = tid; i < TTT * E; i += 128) {
        int tt = i >> 7, k = i & 127;
        int idx = x[b * TT + t0 + tt];
        e[tt][k] = emb[(size_t)idx * E + k];
    }
    __syncthreads();
    int j = tid;                       // owns j and j+128
    const u64* wfp = (const u64*)g_p1f;
    const u64* wbp = (const u64*)g_p1b;
    u64 af0[TTT], af1[TTT], ab0[TTT], ab1[TTT];
#pragma unroll
    for (int tt = 0; tt < TTT; tt++) { af0[tt] = af1[tt] = ab0[tt] = ab1[tt] = 0ull; }
#pragma unroll 2
    for (int kp = 0; kp < 64; kp++) {
        u64 wf0 = wfp[kp * H + j];
        u64 wf1 = wfp[kp * H + j + 128];
        u64 wb0 = wbp[kp * H + j];
        u64 wb1 = wbp[kp * H + j + 128];
#pragma unroll
        for (int tt = 0; tt < TTT; tt++) {
            u64 ev = *(const u64*)&e[tt][2 * kp];
            af0[tt] = ffma2(ev, wf0, af0[tt]);
            af1[tt] = ffma2(ev, wf1, af1[tt]);
            ab0[tt] = ffma2(ev, wb0, ab0[tt]);
            ab1[tt] = ffma2(ev, wb1, ab1[tt]);
        }
    }
    float bf0 = g_b1f[j], bf1 = g_b1f[j + 128];
    float bb0 = g_b1b[j], bb1 = g_b1b[j + 128];
#pragma unroll
    for (int tt = 0; tt < TTT; tt++) {
        size_t o = ((size_t)(b * TT + t0 + tt)) * H;
        float2 v;
        v = unpk(af0[tt]); g_xp1f[o + j]       = v.x + v.y + bf0;
        v = unpk(af1[tt]); g_xp1f[o + j + 128] = v.x + v.y + bf1;
        v = unpk(ab0[tt]); g_xp1b[o + j]       = v.x + v.y + bb0;
        v = unpk(ab1[tt]); g_xp1b[o + j + 128] = v.x + v.y + bb1;
    }
}

// ---------------- layer-2 input projection: 128 thr, JB=2, TTT=8 --------------
__global__ __launch_bounds__(128) void proj2_kernel()
{
    __shared__ __align__(16) float e[TTT * 2 * H];  // 16KB
    int b = blockIdx.y, t0 = blockIdx.x * TTT;
    const float* in = g_o1 + ((size_t)(b * TT + t0)) * (2 * H);
    for (int i = threadIdx.x; i < TTT * 2 * H; i += 128) e[i] = in[i];
    __syncthreads();
    int j = threadIdx.x;
    const u64* wfp = (const u64*)g_p2f;
    const u64* wbp = (const u64*)g_p2b;
    u64 af0[TTT], af1[TTT], ab0[TTT], ab1[TTT];
#pragma unroll
    for (int tt = 0; tt < TTT; tt++) { af0[tt] = af1[tt] = ab0[tt] = ab1[tt] = 0ull; }
#pragma unroll 2
    for (int kp = 0; kp < 256; kp++) {
        u64 wf0 = wfp[kp * H + j];
        u64 wf1 = wfp[kp * H + j + 128];
        u64 wb0 = wbp[kp * H + j];
        u64 wb1 = wbp[kp * H + j + 128];
#pragma unroll
        for (int tt = 0; tt < TTT; tt++) {
            u64 ev = *(const u64*)&e[tt * (2 * H) + 2 * kp];
            af0[tt] = ffma2(ev, wf0, af0[tt]);
            af1[tt] = ffma2(ev, wf1, af1[tt]);
            ab0[tt] = ffma2(ev, wb0, ab0[tt]);
            ab1[tt] = ffma2(ev, wb1, ab1[tt]);
        }
    }
    float bf0 = g_b2f[j], bf1 = g_b2f[j + 128];
    float bb0 = g_b2b[j], bb1 = g_b2b[j + 128];
#pragma unroll
    for (int tt = 0; tt < TTT; tt++) {
        size_t o = ((size_t)(b * TT + t0 + tt)) * H;
        float2 v;
        v = unpk(af0[tt]); g_xp2f[o + j]       = v.x + v.y + bf0;
        v = unpk(af1[tt]); g_xp2f[o + j + 128] = v.x + v.y + bf1;
        v = unpk(ab0[tt]); g_xp2b[o + j]       = v.x + v.y + bb0;
        v = unpk(ab1[tt]); g_xp2b[o + j + 128] = v.x + v.y + bb1;
    }
}

// ---------------- recurrence: one CTA per (b,dir), 512 threads, split-K -------
// Thread (j = tid&255, half = tid>>8) owns k-pairs [half*64, half*64+64):
// 40 pairs in registers, 24 pairs in smem [slot][j] (8B, conflict-free).
// h double-buffered in smem, read broadcast as ulonglong2. Half 1 deposits its
// partial in smem; half 0 adds, applies tanh, writes h and the output.
constexpr int PREG = 40;   // reg pairs per thread
constexpr int PSM = 24;    // smem pairs per thread (x2 halves = 48 slots)
constexpr int RNN_SMEM_BYTES = 48 * H * 8 + 2 * H * 4 + H * 4;  // 101376 B

__global__ __launch_bounds__(512, 1) void rnn_kernel(
    const float* __restrict__ whh_f, const float* __restrict__ whh_b, int layer)
{
    extern __shared__ char smraw[];
    u64* ws2 = (u64*)smraw;                             // [48][256]
    float* hb = (float*)(smraw + 48 * H * 8);           // [2][256]
    float* partial = hb + 2 * H;                        // [256]

    int b = blockIdx.x >> 1;
    int dir = blockIdx.x & 1;
    const float* whh = dir ? whh_b : whh_f;
    const float* xp = layer ? (dir ? g_xp2b : g_xp2f) : (dir ? g_xp1b : g_xp1f);
    float* out = layer ? g_o2 : g_o1;

    int j = threadIdx.x & 255;
    int half = threadIdx.x >> 8;

    const u64* wrow = (const u64*)(whh + (size_t)j * H) + half * 64;
    u64 wr[PREG];
#pragma unroll
    for (int r = 0; r < PREG; r++) wr[r] = wrow[r];
    for (int r = 0; r < PSM; r++) ws2[(half * PSM + r) * H + j] = wrow[PREG + r];
    if (half == 0) { hb[j] = 0.f; hb[H + j] = 0.f; }
    __syncthreads();

    const float* xpBase = xp + (size_t)b * TT * H + j;
    float* outBase = out + (size_t)b * TT * (2 * H) + dir * H + j;
    const u64* wsBase = ws2 + (half * PSM) * H + j;

    int p = 0;
    for (int s = 0; s < TT; s++) {
        int t = dir ? (TT - 1 - s) : s;
        float xpv = (half == 0) ? xpBase[(size_t)t * H] : 0.f;
        const ulonglong2* h2 = (const ulonglong2*)(hb + p * H) + half * 32;
        u64 a0 = 0ull, a1 = 0ull, a2 = 0ull, a3 = 0ull;
#pragma unroll
        for (int q = 0; q < PREG / 2; q++) {     // 40 reg pairs
            ulonglong2 hq = h2[q];
            if (q & 1) {
                a2 = ffma2(hq.x, wr[2 * q], a2);
                a3 = ffma2(hq.y, wr[2 * q + 1], a3);
            } else {
                a0 = ffma2(hq.x, wr[2 * q], a0);
                a1 = ffma2(hq.y, wr[2 * q + 1], a1);
            }
        }
#pragma unroll
        for (int i = 0; i < PSM / 2; i++) {      // 24 smem pairs
            ulonglong2 hq = h2[PREG / 2 + i];
            u64 w0 = wsBase[(2 * i) * H];
            u64 w1v = wsBase[(2 * i + 1) * H];
            if (i & 1) {
                a2 = ffma2(hq.x, w0, a2);
                a3 = ffma2(hq.y, w1v, a3);
            } else {
                a0 = ffma2(hq.x, w0, a0);
                a1 = ffma2(hq.y, w1v, a1);
            }
        }
        float2 f = unpk(fadd2(fadd2(a0, a1), fadd2(a2, a3)));
        float part = f.x + f.y;
        if (half == 1) partial[j] = part;
        __syncthreads();
        if (half == 0) {
            float hn = tanhf(part + partial[j] + xpv);
            hb[(p ^ 1) * H + j] = hn;
            outBase[(size_t)t * (2 * H)] = hn;
        }
        __syncthreads();
        p ^= 1;
    }
}

// ---------------- tail: last/mean + LN + FC1(relu) + FC2 ----------------------
__global__ __launch_bounds__(256) void tail_kernel(
    const float* __restrict__ ln_g, const float* __restrict__ ln_b,
    const float* __restrict__ b1, const float* __restrict__ b2,
    float* __restrict__ outp)
{
    __shared__ __align__(16) float h_s[1024];
    __shared__ __align__(16) float hn_s[1024];
    __shared__ float red[256];
    __shared__ __align__(16) float r_s[512];
    int b = blockIdx.x, j = threadIdx.x;

    const float* base = g_o2 + (size_t)b * TT * (2 * H);
    float s0 = 0.f, s1 = 0.f;
    for (int t = 0; t < TT; t++) {
        s0 += base[(size_t)t * (2 * H) + j];
        s1 += base[(size_t)t * (2 * H) + H + j];
    }
    h_s[j]       = base[(size_t)(TT - 1) * (2 * H) + j];
    h_s[H + j]   = base[(size_t)(TT - 1) * (2 * H) + H + j];
    h_s[512 + j] = s0 * (1.f / 512.f);
    h_s[768 + j] = s1 * (1.f / 512.f);
    __syncthreads();

    red[j] = h_s[j] + h_s[j + 256] + h_s[j + 512] + h_s[j + 768];
    __syncthreads();
    for (int off = 128; off > 0; off >>= 1) {
        if (j < off) red[j] += red[j + off];
        __syncthreads();
    }
    float mu = red[0] * (1.f / 1024.f);
    __syncthreads();
    float d0 = h_s[j] - mu, d1 = h_s[j + 256] - mu,
          d2 = h_s[j + 512] - mu, d3 = h_s[j + 768] - mu;
    red[j] = d0 * d0 + d1 * d1 + d2 * d2 + d3 * d3;
    __syncthreads();
    for (int off = 128; off > 0; off >>= 1) {
        if (j < off) red[j] += red[j + off];
        __syncthreads();
    }
    float var = red[0] * (1.f / 1024.f);
    float sc = rsqrtf(var + 1e-5f);
    hn_s[j]       = d0 * sc * ln_g[j]       + ln_b[j];
    hn_s[j + 256] = d1 * sc * ln_g[j + 256] + ln_b[j + 256];
    hn_s[j + 512] = d2 * sc * ln_g[j + 512] + ln_b[j + 512];
    hn_s[j + 768] = d3 * sc * ln_g[j + 768] + ln_b[j + 768];
    __syncthreads();

    {   // FC1: 1024 -> 512, relu
        const u64* hnu = (const u64*)hn_s;
        const u64* w1u = (const u64*)g_w1p;
        u64 acc0 = 0ull, acc1 = 0ull;
#pragma unroll 4
        for (int kp = 0; kp < 512; kp++) {
            u64 hv = hnu[kp];
            acc0 = ffma2(hv, w1u[kp * 512 + j], acc0);
            acc1 = ffma2(hv, w1u[kp * 512 + j + 256], acc1);
        }
        float2 f0 = unpk(acc0), f1 = unpk(acc1);
        r_s[j]       = fmaxf(f0.x + f0.y + b1[j], 0.f);
        r_s[j + 256] = fmaxf(f1.x + f1.y + b1[j + 256], 0.f);
    }
    __syncthreads();

    {   // FC2: 512 -> 256
        const u64* rsu = (const u64*)r_s;
        const u64* w2u = (const u64*)g_w2p;
        u64 acc = 0ull;
#pragma unroll 4
        for (int kp = 0; kp < 256; kp++)
            acc = ffma2(rsu[kp], w2u[kp * 256 + j], acc);
        float2 f = unpk(acc);
        outp[b * 256 + j] = f.x + f.y + b2[j];
    }
}

// ---------------- launch ------------------------------------------------------
extern "C" void kernel_launch(void* const* d_in, const int* in_sizes, int n_in,
                              void* d_out, int out_size)
{
    const int*   x      = (const int*)  d_in[0];
    const float* emb    = (const float*)d_in[1];
    const float* r1_wif = (const float*)d_in[2];
    const float* r1_whf = (const float*)d_in[3];
    const float* r1_bif = (const float*)d_in[4];
    const float* r1_bhf = (const float*)d_in[5];
    const float* r1_wib = (const float*)d_in[6];
    const float* r1_whb = (const float*)d_in[7];
    const float* r1_bib = (const float*)d_in[8];
    const float* r1_bhb = (const float*)d_in[9];
    const float* r2_wif = (const float*)d_in[10];
    const float* r2_whf = (const float*)d_in[11];
    const float* r2_bif = (const float*)d_in[12];
    const float* r2_bhf = (const float*)d_in[13];
    const float* r2_wib = (const float*)d_in[14];
    const float* r2_whb = (const float*)d_in[15];
    const float* r2_bib = (const float*)d_in[16];
    const float* r2_bhb = (const float*)d_in[17];
    const float* ln_g   = (const float*)d_in[18];
    const float* ln_b   = (const float*)d_in[19];
    const float* w1     = (const float*)d_in[20];
    const float* b1     = (const float*)d_in[21];
    const float* w2     = (const float*)d_in[22];
    const float* b2     = (const float*)d_in[23];
    float* outp = (float*)d_out;

    cudaFuncSetAttribute(rnn_kernel,
                         cudaFuncAttributeMaxDynamicSharedMemorySize,
                         RNN_SMEM_BYTES);

    prep_kernel<<<1024, 256>>>(r1_wif, r1_wib, r1_bif, r1_bhf, r1_bib, r1_bhb,
                               r2_wif, r2_wib, r2_bif, r2_bhf, r2_bib, r2_bhb,
                               w1, w2);

    dim3 gproj(TT / TTT, B);
    proj1_kernel<<<gproj, 128>>>(x, emb);
    rnn_kernel<<<2 * B, 512, RNN_SMEM_BYTES>>>(r1_whf, r1_whb, 0);
    proj2_kernel<<<gproj, 128>>>();
    rnn_kernel<<<2 * B, 512, RNN_SMEM_BYTES>>>(r2_whf, r2_whb, 1);
    tail_kernel<<<B, 256>>>(ln_g, ln_b, b1, b2, outp);
}